// round 6
// baseline (speedup 1.0000x reference)
#include <cuda_runtime.h>

#define NB   16
#define NH   16
#define SQL  1024
#define SKVL 1024
#define DH   64
#define EMB  1024
#define QT   32
#define KT   64
#define NTHR 256
#define NKT  (SKVL/KT)
#define EPITCH 1032   // float4-aligned, 2p-row stride -> <=2-way conflicts
#define KPITCH 68
#define QPITCH 68

__device__ __forceinline__ float fast_tanh(float x) {
    float y;
    asm("tanh.approx.f32 %0, %1;" : "=f"(y) : "f"(x));
    return y;
}

__global__ __launch_bounds__(NTHR, 1)
void attn_fused_kernel(const float* __restrict__ Qg, const float* __restrict__ Kg,
                       const float* __restrict__ Vg, const int* __restrict__ maskg,
                       float* __restrict__ outg, float* __restrict__ wg)
{
    extern __shared__ float sm[];
    float* Em     = sm;                   // QT*EPITCH  (132 KB)
    float* Ks     = Em + QT*EPITCH;       // 2*KT*KPITCH
    float* Vs     = Ks + 2*KT*KPITCH;     // 2*KT*KPITCH
    float* Qs     = Vs + 2*KT*KPITCH;     // QT*QPITCH
    float* mfull  = Qs + QT*QPITCH;       // SKVL
    float* rowsum = mfull + SKVL;         // QT
    float* invs   = rowsum + QT;          // QT

    const int t = threadIdx.x;
    const int p = t & 15;      // q-pair index: rows 2p, 2p+1
    const int g = t >> 4;      // k-group (S phase) / d-group (AV phase)
    const int b = blockIdx.y;
    const int q0 = blockIdx.x * QT;

    for (int i = t; i < SKVL; i += NTHR)
        mfull[i] = (maskg[b*SKVL + i] != 0) ? 0.0f : 1.0f;

    for (int h = 0; h < NH; h++) {
        // ---- stage Q tile (32 x 64) into shared, coalesced
        #pragma unroll
        for (int i = 0; i < 2; i++) {
            int idx = t + i*NTHR;
            int row = idx >> 4, c4 = (idx & 15)*4;
            *(float4*)(Qs + row*QPITCH + c4) =
                *(const float4*)(Qg + ((size_t)(b*SQL + q0 + row))*EMB + h*DH + c4);
        }
        if (t < QT) rowsum[t] = 0.0f;

        // ---- load kv tile 0 into buffer 0
        {
            const float* kb = Kg + ((size_t)(b*SKVL))*EMB + h*DH;
            const float* vb = Vg + ((size_t)(b*SKVL))*EMB + h*DH;
            #pragma unroll
            for (int i = 0; i < 4; i++) {
                int idx = t + i*NTHR;
                int row = idx >> 4, c4 = (idx & 15)*4;
                *(float4*)(Ks + row*KPITCH + c4) = *(const float4*)(kb + (size_t)row*EMB + c4);
                *(float4*)(Vs + row*KPITCH + c4) = *(const float4*)(vb + (size_t)row*EMB + c4);
            }
        }
        __syncthreads();

        float o00=0,o01=0,o02=0,o03=0;   // O[2p][g*4..+3]
        float o10=0,o11=0,o12=0,o13=0;   // O[2p+1][g*4..+3]
        float psum0 = 0.0f, psum1 = 0.0f;

        for (int kt = 0; kt < NKT; kt++) {
            const int cur = kt & 1;
            // ---- prefetch next tile into registers
            float4 kpre[4], vpre[4];
            if (kt < NKT-1) {
                const int kv0 = (kt+1)*KT;
                const float* kb = Kg + ((size_t)(b*SKVL + kv0))*EMB + h*DH;
                const float* vb = Vg + ((size_t)(b*SKVL + kv0))*EMB + h*DH;
                #pragma unroll
                for (int i = 0; i < 4; i++) {
                    int idx = t + i*NTHR;
                    int row = idx >> 4, c4 = (idx & 15)*4;
                    kpre[i] = *(const float4*)(kb + (size_t)row*EMB + c4);
                    vpre[i] = *(const float4*)(vb + (size_t)row*EMB + c4);
                }
            }

            // ---- S phase: scores for q rows {2p,2p+1} x k rows {4g..4g+3}
            float s0[4] = {0,0,0,0};
            float s1[4] = {0,0,0,0};
            const float* kb0 = Ks + cur*(KT*KPITCH) + (g*4)*KPITCH;
            #pragma unroll
            for (int half = 0; half < 2; half++) {
                float4 qa[8], qb[8];
                const float* qp0 = Qs + (2*p)*QPITCH + half*32;
                const float* qp1 = qp0 + QPITCH;
                #pragma unroll
                for (int i = 0; i < 8; i++) {
                    qa[i] = *(const float4*)(qp0 + i*4);
                    qb[i] = *(const float4*)(qp1 + i*4);
                }
                #pragma unroll
                for (int d4 = 0; d4 < 8; d4++) {
                    const float* kd = kb0 + half*32 + d4*4;
                    float4 k0 = *(const float4*)(kd + 0*KPITCH);
                    float4 k1 = *(const float4*)(kd + 1*KPITCH);
                    float4 k2 = *(const float4*)(kd + 2*KPITCH);
                    float4 k3 = *(const float4*)(kd + 3*KPITCH);
                    float4 xa = qa[d4], xb = qb[d4];
                    s0[0] += xa.x*k0.x + xa.y*k0.y + xa.z*k0.z + xa.w*k0.w;
                    s0[1] += xa.x*k1.x + xa.y*k1.y + xa.z*k1.z + xa.w*k1.w;
                    s0[2] += xa.x*k2.x + xa.y*k2.y + xa.z*k2.z + xa.w*k2.w;
                    s0[3] += xa.x*k3.x + xa.y*k3.y + xa.z*k3.z + xa.w*k3.w;
                    s1[0] += xb.x*k0.x + xb.y*k0.y + xb.z*k0.z + xb.w*k0.w;
                    s1[1] += xb.x*k1.x + xb.y*k1.y + xb.z*k1.z + xb.w*k1.w;
                    s1[2] += xb.x*k2.x + xb.y*k2.y + xb.z*k2.z + xb.w*k2.w;
                    s1[3] += xb.x*k3.x + xb.y*k3.y + xb.z*k3.z + xb.w*k3.w;
                }
            }
            // epilogue: clip-tanh + exp + mask, write E, accumulate row sums
            {
                float4 m4 = *(const float4*)(mfull + kt*KT + g*4);
                float mm[4] = {m4.x, m4.y, m4.z, m4.w};
                float e0[4], e1[4];
                #pragma unroll
                for (int i = 0; i < 4; i++) {
                    e0[i] = __expf(10.0f * fast_tanh(s0[i] * 0.125f)) * mm[i];
                    e1[i] = __expf(10.0f * fast_tanh(s1[i] * 0.125f)) * mm[i];
                    psum0 += e0[i];
                    psum1 += e1[i];
                }
                *(float4*)(Em + (2*p)*EPITCH   + kt*KT + g*4) = make_float4(e0[0],e0[1],e0[2],e0[3]);
                *(float4*)(Em + (2*p+1)*EPITCH + kt*KT + g*4) = make_float4(e1[0],e1[1],e1[2],e1[3]);
            }
            __syncthreads();

            // ---- AV phase: O[2p..2p+1][g*4..+3] += E * V
            {
                const float* vb0 = Vs + cur*(KT*KPITCH) + g*4;
                const float* e0p = Em + (2*p)*EPITCH + kt*KT;
                const float* e1p = e0p + EPITCH;
                #pragma unroll
                for (int k4 = 0; k4 < 16; k4++) {
                    float4 ea = *(const float4*)(e0p + k4*4);
                    float4 eb = *(const float4*)(e1p + k4*4);
                    float ear[4] = {ea.x, ea.y, ea.z, ea.w};
                    float ebr[4] = {eb.x, eb.y, eb.z, eb.w};
                    #pragma unroll
                    for (int j = 0; j < 4; j++) {
                        float4 vv = *(const float4*)(vb0 + (k4*4 + j)*KPITCH);
                        o00 += ear[j]*vv.x; o01 += ear[j]*vv.y; o02 += ear[j]*vv.z; o03 += ear[j]*vv.w;
                        o10 += ebr[j]*vv.x; o11 += ebr[j]*vv.y; o12 += ebr[j]*vv.z; o13 += ebr[j]*vv.w;
                    }
                }
            }

            // ---- commit prefetched tile
            if (kt < NKT-1) {
                const int nxt = cur ^ 1;
                #pragma unroll
                for (int i = 0; i < 4; i++) {
                    int idx = t + i*NTHR;
                    int row = idx >> 4, c4 = (idx & 15)*4;
                    *(float4*)(Ks + nxt*(KT*KPITCH) + row*KPITCH + c4) = kpre[i];
                    *(float4*)(Vs + nxt*(KT*KPITCH) + row*KPITCH + c4) = vpre[i];
                }
            }
            __syncthreads();
        }

        // ---- head epilogue
        atomicAdd(&rowsum[2*p],   psum0);
        atomicAdd(&rowsum[2*p+1], psum1);
        __syncthreads();
        if (t < QT) invs[t] = 1.0f / rowsum[t];
        __syncthreads();

        {
            float inv0 = invs[2*p], inv1 = invs[2*p+1];
            float* ob0 = outg + ((size_t)(b*SQL + q0 + 2*p))*EMB + h*DH + g*4;
            float* ob1 = ob0 + EMB;
            *(float4*)ob0 = make_float4(o00*inv0, o01*inv0, o02*inv0, o03*inv0);
            *(float4*)ob1 = make_float4(o10*inv1, o11*inv1, o12*inv1, o13*inv1);
        }

        // ---- weights: accumulate head average directly in global (L2-resident)
        {
            float* wbase = wg + ((size_t)(b*SQL + q0))*SKVL;
            if (h == 0) {
                for (int i = t; i < QT*SKVL; i += NTHR) {
                    int qq = i >> 10, kk = i & 1023;
                    wbase[(size_t)qq*SKVL + kk] = Em[qq*EPITCH + kk] * invs[qq];
                }
            } else if (h == NH-1) {
                for (int i = t; i < QT*SKVL; i += NTHR) {
                    int qq = i >> 10, kk = i & 1023;
                    size_t o = (size_t)qq*SKVL + kk;
                    wbase[o] = (wbase[o] + Em[qq*EPITCH + kk] * invs[qq]) * (1.0f/NH);
                }
            } else {
                for (int i = t; i < QT*SKVL; i += NTHR) {
                    int qq = i >> 10, kk = i & 1023;
                    wbase[(size_t)qq*SKVL + kk] += Em[qq*EPITCH + kk] * invs[qq];
                }
            }
        }
        __syncthreads();   // Em/Qs/rowsum reused next head
    }
}

extern "C" void kernel_launch(void* const* d_in, const int* in_sizes, int n_in,
                              void* d_out, int out_size)
{
    const float* Q = (const float*)d_in[0];
    const float* K = (const float*)d_in[1];
    const float* V = (const float*)d_in[2];
    const int*   mask = (const int*)d_in[3];

    float* out = (float*)d_out;                   // attn_output: 16x1024x1024
    float* w   = out + (size_t)NB * SQL * EMB;    // attn_weights: 16x1024x1024

    size_t smem = (size_t)(QT*EPITCH + 4*KT*KPITCH + QT*QPITCH + SKVL + 2*QT) * sizeof(float);
    cudaFuncSetAttribute(attn_fused_kernel, cudaFuncAttributeMaxDynamicSharedMemorySize, (int)smem);

    dim3 grid(SQL/QT, NB);
    attn_fused_kernel<<<grid, NTHR, smem>>>(Q, K, V, mask, out, w);
}

// round 7
// speedup vs baseline: 1.7346x; 1.7346x over previous
#include <cuda_runtime.h>
#include <cstdint>

#define NB   16
#define NH   16
#define SQL  1024
#define SKVL 1024
#define DH   64
#define EMB  1024
#define QT   16
#define KT   32
#define NKT  (SKVL/KT)
#define NTHR 256
#define EPITCH 1025   // stride ≡ 1 mod 32 -> conflict-free across qi lanes
#define KPITCH 68     // 272B rows, 16B-aligned for cp.async

__device__ __forceinline__ float fast_tanh(float x) {
    float y;
    asm("tanh.approx.f32 %0, %1;" : "=f"(y) : "f"(x));
    return y;
}

__device__ __forceinline__ void cp16(uint32_t smem_dst, const void* gsrc) {
    asm volatile("cp.async.cg.shared.global [%0], [%1], 16;" :: "r"(smem_dst), "l"(gsrc));
}
__device__ __forceinline__ void cp_commit() { asm volatile("cp.async.commit_group;"); }
__device__ __forceinline__ void cp_wait0()  { asm volatile("cp.async.wait_group 0;" ::: "memory"); }

__global__ __launch_bounds__(NTHR, 2)
void attn_fused_kernel(const float* __restrict__ Qg, const float* __restrict__ Kg,
                       const float* __restrict__ Vg, const int* __restrict__ maskg,
                       float* __restrict__ outg, float* __restrict__ wg)
{
    extern __shared__ float sm[];
    float* Em     = sm;                     // QT*EPITCH   (65.6 KB)
    float* Ks     = Em + QT*EPITCH;         // 2*KT*KPITCH (17.4 KB)
    float* Vs     = Ks + 2*KT*KPITCH;       // 2*KT*KPITCH (17.4 KB)
    float* mfull  = Vs + 2*KT*KPITCH;       // SKVL (4 KB)
    float* rowsum = mfull + SKVL;           // QT
    float* invs   = rowsum + QT;            // QT

    const int t  = threadIdx.x;
    const int qi = t & 15;      // q row owned by this thread
    const int g  = t >> 4;      // key-pair group (S) / d-group (AV)
    const int b  = blockIdx.y;
    const int q0 = blockIdx.x * QT;

    const uint32_t ks_base = (uint32_t)__cvta_generic_to_shared(Ks);
    const uint32_t vs_base = (uint32_t)__cvta_generic_to_shared(Vs);

    for (int i = t; i < SKVL; i += NTHR)
        mfull[i] = (maskg[b*SKVL + i] != 0) ? 0.0f : 1.0f;

    for (int h = 0; h < NH; h++) {
        // ---- Q row into registers (once per head)
        float qr[DH];
        {
            const float* qp = Qg + ((size_t)(b*SQL + q0 + qi))*EMB + h*DH;
            #pragma unroll
            for (int i = 0; i < DH/4; i++) {
                float4 v = *(const float4*)(qp + i*4);
                qr[i*4+0]=v.x; qr[i*4+1]=v.y; qr[i*4+2]=v.z; qr[i*4+3]=v.w;
            }
        }
        if (t < QT) rowsum[t] = 0.0f;

        const float* kh = Kg + ((size_t)(b*SKVL))*EMB + h*DH;
        const float* vh = Vg + ((size_t)(b*SKVL))*EMB + h*DH;

        // ---- preload tile 0 into buffer 0 (cp.async)
        {
            #pragma unroll
            for (int i = 0; i < 2; i++) {
                int c = t + i*NTHR;              // 0..511 chunks of 16B
                int row = c >> 4, col = (c & 15) * 4;
                cp16(ks_base + (uint32_t)((row*KPITCH + col)*4), kh + (size_t)row*EMB + col);
                cp16(vs_base + (uint32_t)((row*KPITCH + col)*4), vh + (size_t)row*EMB + col);
            }
            cp_commit();
        }
        cp_wait0();
        __syncthreads();

        float o0=0.f,o1=0.f,o2=0.f,o3=0.f;   // O[qi][4g..4g+3]
        float psum = 0.0f;

        for (int kt = 0; kt < NKT; kt++) {
            const int cur = kt & 1;
            // ---- async-load next tile into other buffer
            if (kt < NKT-1) {
                const int kv0 = (kt+1)*KT;
                const int boff = (cur^1) * (KT*KPITCH);
                #pragma unroll
                for (int i = 0; i < 2; i++) {
                    int c = t + i*NTHR;
                    int row = c >> 4, col = (c & 15) * 4;
                    cp16(ks_base + (uint32_t)((boff + row*KPITCH + col)*4),
                         kh + (size_t)(kv0 + row)*EMB + col);
                    cp16(vs_base + (uint32_t)((boff + row*KPITCH + col)*4),
                         vh + (size_t)(kv0 + row)*EMB + col);
                }
                cp_commit();
            }

            // ---- S phase: scores for (qi, keys 2g, 2g+1)
            {
                const float* kb0 = Ks + cur*(KT*KPITCH) + (g*2)*KPITCH;
                float a0=0.f, a1=0.f;
                #pragma unroll
                for (int d4 = 0; d4 < DH/4; d4++) {
                    float4 k0 = *(const float4*)(kb0 + d4*4);
                    float4 k1 = *(const float4*)(kb0 + KPITCH + d4*4);
                    float x0=qr[d4*4+0], x1=qr[d4*4+1], x2=qr[d4*4+2], x3=qr[d4*4+3];
                    a0 += x0*k0.x + x1*k0.y + x2*k0.z + x3*k0.w;
                    a1 += x0*k1.x + x1*k1.y + x2*k1.z + x3*k1.w;
                }
                float m0 = mfull[kt*KT + g*2];
                float m1 = mfull[kt*KT + g*2 + 1];
                float e0 = __expf(10.0f * fast_tanh(a0 * 0.125f)) * m0;
                float e1 = __expf(10.0f * fast_tanh(a1 * 0.125f)) * m1;
                psum += e0 + e1;
                Em[qi*EPITCH + kt*KT + g*2]     = e0;
                Em[qi*EPITCH + kt*KT + g*2 + 1] = e1;
            }
            __syncthreads();   // E visible; K[cur] reads done

            // ---- AV phase: O[qi][4g..4g+3] += E[qi][k] * V[k][4g..4g+3]
            {
                const float* erow = Em + qi*EPITCH + kt*KT;
                const float* vb0  = Vs + cur*(KT*KPITCH) + g*4;
                #pragma unroll
                for (int k = 0; k < KT; k++) {
                    float e = erow[k];
                    float4 vv = *(const float4*)(vb0 + k*KPITCH);
                    o0 += e*vv.x; o1 += e*vv.y; o2 += e*vv.z; o3 += e*vv.w;
                }
            }

            if (kt < NKT-1) cp_wait0();
            __syncthreads();   // AV reads of V[cur]/Em done; next buffer complete
        }

        // ---- head epilogue
        atomicAdd(&rowsum[qi], psum);
        __syncthreads();
        if (t < QT) invs[t] = 1.0f / rowsum[t];
        __syncthreads();

        {
            float inv = invs[qi];
            float* ob = outg + ((size_t)(b*SQL + q0 + qi))*EMB + h*DH + g*4;
            *(float4*)ob = make_float4(o0*inv, o1*inv, o2*inv, o3*inv);
        }

        // ---- weights: accumulate head average directly in global (L2-resident)
        {
            float* wbase = wg + ((size_t)(b*SQL + q0))*SKVL;
            if (h == 0) {
                for (int i = t; i < QT*SKVL; i += NTHR) {
                    int qq = i >> 10, kk = i & 1023;
                    wbase[(size_t)qq*SKVL + kk] = Em[qq*EPITCH + kk] * invs[qq];
                }
            } else if (h == NH-1) {
                for (int i = t; i < QT*SKVL; i += NTHR) {
                    int qq = i >> 10, kk = i & 1023;
                    size_t o = (size_t)qq*SKVL + kk;
                    wbase[o] = (wbase[o] + Em[qq*EPITCH + kk] * invs[qq]) * (1.0f/NH);
                }
            } else {
                for (int i = t; i < QT*SKVL; i += NTHR) {
                    int qq = i >> 10, kk = i & 1023;
                    wbase[(size_t)qq*SKVL + kk] += Em[qq*EPITCH + kk] * invs[qq];
                }
            }
        }
        __syncthreads();   // Em / rowsum reused next head
    }
}

extern "C" void kernel_launch(void* const* d_in, const int* in_sizes, int n_in,
                              void* d_out, int out_size)
{
    const float* Q = (const float*)d_in[0];
    const float* K = (const float*)d_in[1];
    const float* V = (const float*)d_in[2];
    const int*   mask = (const int*)d_in[3];

    float* out = (float*)d_out;                   // attn_output: 16x1024x1024
    float* w   = out + (size_t)NB * SQL * EMB;    // attn_weights: 16x1024x1024

    size_t smem = (size_t)(QT*EPITCH + 4*KT*KPITCH + SKVL + 2*QT) * sizeof(float);
    cudaFuncSetAttribute(attn_fused_kernel, cudaFuncAttributeMaxDynamicSharedMemorySize, (int)smem);

    dim3 grid(SQL/QT, NB);
    attn_fused_kernel<<<grid, NTHR, smem>>>(Q, K, V, mask, out, w);
}